// round 2
// baseline (speedup 1.0000x reference)
#include <cuda_runtime.h>
#include <cuda_bf16.h>
#include <math_constants.h>

// Problem constants (registry shapes)
#define MAX_NODES 100000
#define HIDDEN 128
#define MAX_EDGES 1000000

#define GEMM_BM 64
#define GEMM_BK 32
#define EDGES_PER_BLOCK 8
#define MAX_EDGE_BLOCKS ((MAX_EDGES + EDGES_PER_BLOCK - 1) / EDGES_PER_BLOCK)
#define EXP_BLOCKS 2048

// Scratch (allocation-free rule: __device__ globals)
__device__ float g_A[MAX_NODES * HIDDEN];       // emb @ W1[:128]
__device__ float g_B[MAX_NODES * HIDDEN];       // emb @ W1[128:]
__device__ float g_logits[MAX_EDGES];
__device__ float g_pmax[MAX_EDGE_BLOCKS];
__device__ float g_psum[EXP_BLOCKS];
__device__ float g_max;
__device__ float g_inv;

// ---------------------------------------------------------------------------
// Phase 1: C[n, 0:256] = emb[n, :] @ [W1_top | W1_bot]; split into g_A / g_B.
// ---------------------------------------------------------------------------
__global__ __launch_bounds__(256, 2) void gemm_kernel(
    const float* __restrict__ emb, const float* __restrict__ W1, int M)
{
    __shared__ __align__(16) float sW[GEMM_BK][256];        // 32 KB
    __shared__ __align__(16) float sE[GEMM_BK][GEMM_BM + 4];// transposed emb tile

    const int tid = threadIdx.x;
    const int tx = tid & 15;    // col group 0..15
    const int ty = tid >> 4;    // row group 0..15
    const int m0 = blockIdx.x * GEMM_BM;

    float acc[4][16];
#pragma unroll
    for (int r = 0; r < 4; r++)
#pragma unroll
        for (int c = 0; c < 16; c++) acc[r][c] = 0.0f;

    for (int kc = 0; kc < HIDDEN; kc += GEMM_BK) {
        // Load W chunk: 32 x 256 floats = 2048 float4, 8 per thread (coalesced)
#pragma unroll
        for (int i = 0; i < 8; i++) {
            int idx = tid + i * 256;   // 0..2047
            int kk = idx >> 6;         // 0..31
            int q  = idx & 63;         // float4 index within 256-wide row
            int jj = q * 4;
            const float* src = (jj < HIDDEN)
                ? (W1 + (kc + kk) * HIDDEN + jj)
                : (W1 + (HIDDEN + kc + kk) * HIDDEN + (jj - HIDDEN));
            *(float4*)&sW[kk][jj] = *(const float4*)src;
        }
        // Load emb chunk transposed: 64 rows x 32 k, 2 float4 per thread
#pragma unroll
        for (int i = 0; i < 2; i++) {
            int idx = tid + i * 256;   // 0..511
            int r   = idx >> 3;        // 0..63
            int k4  = (idx & 7) * 4;   // 0,4,...,28
            int row = m0 + r;
            float4 v = make_float4(0.f, 0.f, 0.f, 0.f);
            if (row < M) v = *(const float4*)(emb + (long)row * HIDDEN + kc + k4);
            sE[k4 + 0][r] = v.x; sE[k4 + 1][r] = v.y;
            sE[k4 + 2][r] = v.z; sE[k4 + 3][r] = v.w;
        }
        __syncthreads();

#pragma unroll 8
        for (int kk = 0; kk < GEMM_BK; kk++) {
            float4 a4 = *(float4*)&sE[kk][ty * 4];
            float av[4] = {a4.x, a4.y, a4.z, a4.w};
#pragma unroll
            for (int i = 0; i < 4; i++) {
                float4 w4 = *(float4*)&sW[kk][tx * 4 + i * 64];
                float wv[4] = {w4.x, w4.y, w4.z, w4.w};
#pragma unroll
                for (int r = 0; r < 4; r++) {
                    acc[r][i * 4 + 0] = fmaf(av[r], wv[0], acc[r][i * 4 + 0]);
                    acc[r][i * 4 + 1] = fmaf(av[r], wv[1], acc[r][i * 4 + 1]);
                    acc[r][i * 4 + 2] = fmaf(av[r], wv[2], acc[r][i * 4 + 2]);
                    acc[r][i * 4 + 3] = fmaf(av[r], wv[3], acc[r][i * 4 + 3]);
                }
            }
        }
        __syncthreads();
    }

    // Write: cols [0,128) -> g_A, [128,256) -> g_B. Col c = tx*4 + i*64.
#pragma unroll
    for (int r = 0; r < 4; r++) {
        int row = m0 + ty * 4 + r;
        if (row >= M) continue;
#pragma unroll
        for (int i = 0; i < 4; i++) {
            int c = tx * 4 + i * 64;
            float4 v = make_float4(acc[r][i * 4 + 0], acc[r][i * 4 + 1],
                                   acc[r][i * 4 + 2], acc[r][i * 4 + 3]);
            if (c < HIDDEN)
                *(float4*)(g_A + (long)row * HIDDEN + c) = v;
            else
                *(float4*)(g_B + (long)row * HIDDEN + (c - HIDDEN)) = v;
        }
    }
}

// ---------------------------------------------------------------------------
// Phase 2: per-edge logit. One warp per edge: lane l handles features 4l..4l+3.
// Indices are int32 (JAX default config downcasts int64 -> int32).
// ---------------------------------------------------------------------------
__global__ __launch_bounds__(256) void edge_kernel(
    const int* __restrict__ srcs, const int* __restrict__ dsts,
    const float* __restrict__ b1, const float* __restrict__ W2,
    const float* __restrict__ b2, int E, int M)
{
    const int lane = threadIdx.x & 31;
    const int warp = threadIdx.x >> 5;
    const int e = blockIdx.x * EDGES_PER_BLOCK + warp;

    float4 b1v = *(const float4*)(b1 + lane * 4);
    float4 w2v = *(const float4*)(W2 + lane * 4);

    float logit = -CUDART_INF_F;
    if (e < E) {
        int s = srcs[e];
        int t = dsts[e];
        // Defensive clamp: converts any index-dtype surprise into a clean
        // rel_err failure instead of an illegal access.
        if ((unsigned)s >= (unsigned)M) s = 0;
        if ((unsigned)t >= (unsigned)M) t = 0;
        float4 av = *(const float4*)(g_A + (long)s * HIDDEN + lane * 4);
        float4 bv = *(const float4*)(g_B + (long)t * HIDDEN + lane * 4);
        float h0 = fmaxf(av.x + bv.x + b1v.x, 0.0f);
        float h1 = fmaxf(av.y + bv.y + b1v.y, 0.0f);
        float h2 = fmaxf(av.z + bv.z + b1v.z, 0.0f);
        float h3 = fmaxf(av.w + bv.w + b1v.w, 0.0f);
        float p = h0 * w2v.x + h1 * w2v.y + h2 * w2v.z + h3 * w2v.w;
#pragma unroll
        for (int o = 16; o > 0; o >>= 1)
            p += __shfl_down_sync(0xffffffffu, p, o);
        if (lane == 0) {
            logit = p + b2[0];
            g_logits[e] = logit;
        }
    }

    __shared__ float smax[EDGES_PER_BLOCK];
    if (lane == 0) smax[warp] = logit;
    __syncthreads();
    if (threadIdx.x == 0) {
        float m = smax[0];
#pragma unroll
        for (int i = 1; i < EDGES_PER_BLOCK; i++) m = fmaxf(m, smax[i]);
        g_pmax[blockIdx.x] = m;
    }
}

// ---------------------------------------------------------------------------
// Phase 3: softmax (deterministic two-level reductions)
// ---------------------------------------------------------------------------
__global__ __launch_bounds__(1024) void reduce_max_kernel(int n)
{
    __shared__ float s[1024];
    float m = -CUDART_INF_F;
    for (int i = threadIdx.x; i < n; i += 1024) m = fmaxf(m, g_pmax[i]);
    s[threadIdx.x] = m;
    __syncthreads();
#pragma unroll
    for (int o = 512; o > 0; o >>= 1) {
        if (threadIdx.x < o) s[threadIdx.x] = fmaxf(s[threadIdx.x], s[threadIdx.x + o]);
        __syncthreads();
    }
    if (threadIdx.x == 0) g_max = s[0];
}

__global__ __launch_bounds__(256) void exp_kernel(float* __restrict__ out, int E)
{
    const float m = g_max;
    float acc = 0.0f;
    for (int i = blockIdx.x * 256 + threadIdx.x; i < E; i += EXP_BLOCKS * 256) {
        float p = expf(g_logits[i] - m);
        out[i] = p;
        acc += p;
    }
    __shared__ float s[256];
    s[threadIdx.x] = acc;
    __syncthreads();
#pragma unroll
    for (int o = 128; o > 0; o >>= 1) {
        if (threadIdx.x < o) s[threadIdx.x] += s[threadIdx.x + o];
        __syncthreads();
    }
    if (threadIdx.x == 0) g_psum[blockIdx.x] = s[0];
}

__global__ __launch_bounds__(1024) void reduce_sum_kernel()
{
    __shared__ float s[1024];
    float a = 0.0f;
    for (int i = threadIdx.x; i < EXP_BLOCKS; i += 1024) a += g_psum[i];
    s[threadIdx.x] = a;
    __syncthreads();
#pragma unroll
    for (int o = 512; o > 0; o >>= 1) {
        if (threadIdx.x < o) s[threadIdx.x] += s[threadIdx.x + o];
        __syncthreads();
    }
    if (threadIdx.x == 0) g_inv = 1.0f / s[0];
}

__global__ __launch_bounds__(256) void scale_kernel(float* __restrict__ out, int E)
{
    const float v = g_inv;
    for (int i = blockIdx.x * 256 + threadIdx.x; i < E; i += EXP_BLOCKS * 256)
        out[i] *= v;
}

// ---------------------------------------------------------------------------
extern "C" void kernel_launch(void* const* d_in, const int* in_sizes, int n_in,
                              void* d_out, int out_size)
{
    const float* emb = (const float*)d_in[0];
    const int*   lm  = (const int*)d_in[1];   // int32: JAX x64-disabled downcast
    const float* W1  = (const float*)d_in[2];
    const float* b1  = (const float*)d_in[3];
    const float* W2  = (const float*)d_in[4];
    const float* b2  = (const float*)d_in[5];
    float* out = (float*)d_out;

    const int M = in_sizes[0] / HIDDEN;       // number of nodes
    const int E = in_sizes[1] / 2;            // number of edges
    const int* srcs = lm;
    const int* dsts = lm + E;

    const int gemm_blocks = (M + GEMM_BM - 1) / GEMM_BM;
    const int edge_blocks = (E + EDGES_PER_BLOCK - 1) / EDGES_PER_BLOCK;

    gemm_kernel<<<gemm_blocks, 256>>>(emb, W1, M);
    edge_kernel<<<edge_blocks, 256>>>(srcs, dsts, b1, W2, b2, E, M);
    reduce_max_kernel<<<1, 1024>>>(edge_blocks);
    exp_kernel<<<EXP_BLOCKS, 256>>>(out, E);
    reduce_sum_kernel<<<1, 1024>>>();
    scale_kernel<<<EXP_BLOCKS, 256>>>(out, E);
}

// round 3
// speedup vs baseline: 1.1014x; 1.1014x over previous
#include <cuda_runtime.h>
#include <cuda_fp16.h>
#include <math_constants.h>

// Problem constants (registry shapes)
#define MAX_NODES 100000
#define HIDDEN 128
#define MAX_EDGES 1000000

#define GEMM_BM 64
#define GEMM_BK 32
#define EDGES_PER_BLOCK 8
#define MAX_EDGE_BLOCKS ((MAX_EDGES + EDGES_PER_BLOCK - 1) / EDGES_PER_BLOCK)
#define EXP_BLOCKS 2048

// Scratch (allocation-free rule: __device__ globals)
// fp16 tables: 25.6 MB each -> both fit in L2 (126 MB) for the edge gather.
__device__ __half g_A[MAX_NODES * HIDDEN];      // emb @ W1[:128] + b1 (folded)
__device__ __half g_B[MAX_NODES * HIDDEN];      // emb @ W1[128:]
__device__ float g_logits[MAX_EDGES];
__device__ float g_pmax[MAX_EDGE_BLOCKS];
__device__ float g_psum[EXP_BLOCKS];
__device__ float g_max;
__device__ float g_inv;

// ---------------------------------------------------------------------------
// Phase 1: C[n, 0:256] = emb[n, :] @ [W1_top | W1_bot]; split into g_A / g_B
// (fp16, with b1 folded into the A half).
// ---------------------------------------------------------------------------
__global__ __launch_bounds__(256, 2) void gemm_kernel(
    const float* __restrict__ emb, const float* __restrict__ W1,
    const float* __restrict__ b1, int M)
{
    __shared__ __align__(16) float sW[GEMM_BK][256];        // 32 KB
    __shared__ __align__(16) float sE[GEMM_BK][GEMM_BM + 4];// transposed emb tile

    const int tid = threadIdx.x;
    const int tx = tid & 15;    // col group 0..15
    const int ty = tid >> 4;    // row group 0..15
    const int m0 = blockIdx.x * GEMM_BM;

    float acc[4][16];
#pragma unroll
    for (int r = 0; r < 4; r++)
#pragma unroll
        for (int c = 0; c < 16; c++) acc[r][c] = 0.0f;

    for (int kc = 0; kc < HIDDEN; kc += GEMM_BK) {
        // Load W chunk: 32 x 256 floats = 2048 float4, 8 per thread (coalesced)
#pragma unroll
        for (int i = 0; i < 8; i++) {
            int idx = tid + i * 256;   // 0..2047
            int kk = idx >> 6;         // 0..31
            int q  = idx & 63;         // float4 index within 256-wide row
            int jj = q * 4;
            const float* src = (jj < HIDDEN)
                ? (W1 + (kc + kk) * HIDDEN + jj)
                : (W1 + (HIDDEN + kc + kk) * HIDDEN + (jj - HIDDEN));
            *(float4*)&sW[kk][jj] = *(const float4*)src;
        }
        // Load emb chunk transposed: 64 rows x 32 k, 2 float4 per thread
#pragma unroll
        for (int i = 0; i < 2; i++) {
            int idx = tid + i * 256;   // 0..511
            int r   = idx >> 3;        // 0..63
            int k4  = (idx & 7) * 4;   // 0,4,...,28
            int row = m0 + r;
            float4 v = make_float4(0.f, 0.f, 0.f, 0.f);
            if (row < M) v = *(const float4*)(emb + (long)row * HIDDEN + kc + k4);
            sE[k4 + 0][r] = v.x; sE[k4 + 1][r] = v.y;
            sE[k4 + 2][r] = v.z; sE[k4 + 3][r] = v.w;
        }
        __syncthreads();

#pragma unroll 8
        for (int kk = 0; kk < GEMM_BK; kk++) {
            float4 a4 = *(float4*)&sE[kk][ty * 4];
            float av[4] = {a4.x, a4.y, a4.z, a4.w};
#pragma unroll
            for (int i = 0; i < 4; i++) {
                float4 w4 = *(float4*)&sW[kk][tx * 4 + i * 64];
                float wv[4] = {w4.x, w4.y, w4.z, w4.w};
#pragma unroll
                for (int r = 0; r < 4; r++) {
                    acc[r][i * 4 + 0] = fmaf(av[r], wv[0], acc[r][i * 4 + 0]);
                    acc[r][i * 4 + 1] = fmaf(av[r], wv[1], acc[r][i * 4 + 1]);
                    acc[r][i * 4 + 2] = fmaf(av[r], wv[2], acc[r][i * 4 + 2]);
                    acc[r][i * 4 + 3] = fmaf(av[r], wv[3], acc[r][i * 4 + 3]);
                }
            }
        }
        __syncthreads();
    }

    // Epilogue: col c = tx*4 + i*64. cols [0,128) -> g_A (+ b1), else g_B.
#pragma unroll
    for (int r = 0; r < 4; r++) {
        int row = m0 + ty * 4 + r;
        if (row >= M) continue;
#pragma unroll
        for (int i = 0; i < 4; i++) {
            int c = tx * 4 + i * 64;
            float v0 = acc[r][i * 4 + 0], v1 = acc[r][i * 4 + 1];
            float v2 = acc[r][i * 4 + 2], v3 = acc[r][i * 4 + 3];
            if (c < HIDDEN) {
                v0 += __ldg(b1 + c + 0); v1 += __ldg(b1 + c + 1);
                v2 += __ldg(b1 + c + 2); v3 += __ldg(b1 + c + 3);
                __half2 h01 = __floats2half2_rn(v0, v1);
                __half2 h23 = __floats2half2_rn(v2, v3);
                uint2 pack = make_uint2(*(unsigned*)&h01, *(unsigned*)&h23);
                *(uint2*)(g_A + (size_t)row * HIDDEN + c) = pack;
            } else {
                __half2 h01 = __floats2half2_rn(v0, v1);
                __half2 h23 = __floats2half2_rn(v2, v3);
                uint2 pack = make_uint2(*(unsigned*)&h01, *(unsigned*)&h23);
                *(uint2*)(g_B + (size_t)row * HIDDEN + (c - HIDDEN)) = pack;
            }
        }
    }
}

// ---------------------------------------------------------------------------
// Phase 2: per-edge logit. One warp per edge: lane l handles features 4l..4l+3.
// logit[e] = sum_j relu(A'[s][j] + B[t][j]) * W2[j] + b2   (b1 folded into A')
// ---------------------------------------------------------------------------
__global__ __launch_bounds__(256) void edge_kernel(
    const int* __restrict__ srcs, const int* __restrict__ dsts,
    const float* __restrict__ W2, const float* __restrict__ b2,
    int E, int M)
{
    const int lane = threadIdx.x & 31;
    const int warp = threadIdx.x >> 5;
    const int e = blockIdx.x * EDGES_PER_BLOCK + warp;

    float4 w2v = *(const float4*)(W2 + lane * 4);

    float logit = -CUDART_INF_F;
    if (e < E) {
        int s = srcs[e];
        int t = dsts[e];
        if ((unsigned)s >= (unsigned)M) s = 0;
        if ((unsigned)t >= (unsigned)M) t = 0;
        uint2 ar = *(const uint2*)(g_A + (size_t)s * HIDDEN + lane * 4);
        uint2 br = *(const uint2*)(g_B + (size_t)t * HIDDEN + lane * 4);
        float2 a01 = __half22float2(*(__half2*)&ar.x);
        float2 a23 = __half22float2(*(__half2*)&ar.y);
        float2 b01 = __half22float2(*(__half2*)&br.x);
        float2 b23 = __half22float2(*(__half2*)&br.y);
        float h0 = fmaxf(a01.x + b01.x, 0.0f);
        float h1 = fmaxf(a01.y + b01.y, 0.0f);
        float h2 = fmaxf(a23.x + b23.x, 0.0f);
        float h3 = fmaxf(a23.y + b23.y, 0.0f);
        float p = h0 * w2v.x + h1 * w2v.y + h2 * w2v.z + h3 * w2v.w;
#pragma unroll
        for (int o = 16; o > 0; o >>= 1)
            p += __shfl_down_sync(0xffffffffu, p, o);
        if (lane == 0) {
            logit = p + b2[0];
            g_logits[e] = logit;
        }
    }

    __shared__ float smax[EDGES_PER_BLOCK];
    if (lane == 0) smax[warp] = logit;
    __syncthreads();
    if (threadIdx.x == 0) {
        float m = smax[0];
#pragma unroll
        for (int i = 1; i < EDGES_PER_BLOCK; i++) m = fmaxf(m, smax[i]);
        g_pmax[blockIdx.x] = m;
    }
}

// ---------------------------------------------------------------------------
// Phase 3: softmax (deterministic two-level reductions)
// ---------------------------------------------------------------------------
__global__ __launch_bounds__(1024) void reduce_max_kernel(int n)
{
    __shared__ float s[1024];
    float m = -CUDART_INF_F;
    for (int i = threadIdx.x; i < n; i += 1024) m = fmaxf(m, g_pmax[i]);
    s[threadIdx.x] = m;
    __syncthreads();
#pragma unroll
    for (int o = 512; o > 0; o >>= 1) {
        if (threadIdx.x < o) s[threadIdx.x] = fmaxf(s[threadIdx.x], s[threadIdx.x + o]);
        __syncthreads();
    }
    if (threadIdx.x == 0) g_max = s[0];
}

__global__ __launch_bounds__(256) void exp_kernel(float* __restrict__ out, int E)
{
    const float m = g_max;
    float acc = 0.0f;
    for (int i = blockIdx.x * 256 + threadIdx.x; i < E; i += EXP_BLOCKS * 256) {
        float p = expf(g_logits[i] - m);
        out[i] = p;
        acc += p;
    }
    __shared__ float s[256];
    s[threadIdx.x] = acc;
    __syncthreads();
#pragma unroll
    for (int o = 128; o > 0; o >>= 1) {
        if (threadIdx.x < o) s[threadIdx.x] += s[threadIdx.x + o];
        __syncthreads();
    }
    if (threadIdx.x == 0) g_psum[blockIdx.x] = s[0];
}

__global__ __launch_bounds__(1024) void reduce_sum_kernel()
{
    __shared__ float s[1024];
    float a = 0.0f;
    for (int i = threadIdx.x; i < EXP_BLOCKS; i += 1024) a += g_psum[i];
    s[threadIdx.x] = a;
    __syncthreads();
#pragma unroll
    for (int o = 512; o > 0; o >>= 1) {
        if (threadIdx.x < o) s[threadIdx.x] += s[threadIdx.x + o];
        __syncthreads();
    }
    if (threadIdx.x == 0) g_inv = 1.0f / s[0];
}

__global__ __launch_bounds__(256) void scale_kernel(float* __restrict__ out, int E)
{
    const float v = g_inv;
    for (int i = blockIdx.x * 256 + threadIdx.x; i < E; i += EXP_BLOCKS * 256)
        out[i] *= v;
}

// ---------------------------------------------------------------------------
extern "C" void kernel_launch(void* const* d_in, const int* in_sizes, int n_in,
                              void* d_out, int out_size)
{
    const float* emb = (const float*)d_in[0];
    const int*   lm  = (const int*)d_in[1];   // int32 (JAX x64-disabled)
    const float* W1  = (const float*)d_in[2];
    const float* b1  = (const float*)d_in[3];
    const float* W2  = (const float*)d_in[4];
    const float* b2  = (const float*)d_in[5];
    float* out = (float*)d_out;

    const int M = in_sizes[0] / HIDDEN;       // number of nodes
    const int E = in_sizes[1] / 2;            // number of edges
    const int* srcs = lm;
    const int* dsts = lm + E;

    const int gemm_blocks = (M + GEMM_BM - 1) / GEMM_BM;
    const int edge_blocks = (E + EDGES_PER_BLOCK - 1) / EDGES_PER_BLOCK;

    gemm_kernel<<<gemm_blocks, 256>>>(emb, W1, b1, M);
    edge_kernel<<<edge_blocks, 256>>>(srcs, dsts, W2, b2, E, M);
    reduce_max_kernel<<<1, 1024>>>(edge_blocks);
    exp_kernel<<<EXP_BLOCKS, 256>>>(out, E);
    reduce_sum_kernel<<<1, 1024>>>();
    scale_kernel<<<EXP_BLOCKS, 256>>>(out, E);
}

// round 5
// speedup vs baseline: 1.6726x; 1.5185x over previous
#include <cuda_runtime.h>
#include <cuda_fp16.h>
#include <math_constants.h>
#include <cstdint>

// Problem constants (registry shapes)
#define MAX_NODES 100000
#define HIDDEN 128
#define MAX_EDGES 1000000

#define EDGES_PER_BLOCK 8
#define MAX_EDGE_BLOCKS ((MAX_EDGES + EDGES_PER_BLOCK - 1) / EDGES_PER_BLOCK)
#define EXP_BLOCKS 2048

// Scratch (allocation-free rule: __device__ globals)
__device__ __half g_A[MAX_NODES * HIDDEN];      // emb @ W1[:128] + b1 (folded)
__device__ __half g_B[MAX_NODES * HIDDEN];      // emb @ W1[128:]
__device__ __half g_Wt[256 * 128];              // Wt[n][k] = Wcat[k][n], fp16
__device__ float g_logits[MAX_EDGES];
__device__ float g_pmax[MAX_EDGE_BLOCKS];
__device__ float g_psum[EXP_BLOCKS];
__device__ float g_max;
__device__ float g_inv;

__device__ __forceinline__ uint32_t smem_u32(const void* p) {
    uint32_t a;
    asm("{ .reg .u64 t; cvta.to.shared.u64 t, %1; cvt.u32.u64 %0, t; }"
        : "=r"(a) : "l"(p));
    return a;
}

#define LDSM_X4(r0, r1, r2, r3, addr) asm volatile( \
    "ldmatrix.sync.aligned.m8n8.x4.shared.b16 {%0,%1,%2,%3}, [%4];" \
    : "=r"(r0), "=r"(r1), "=r"(r2), "=r"(r3) : "r"(addr))

#define MMA16816(c, a, b) asm volatile( \
    "mma.sync.aligned.m16n8k16.row.col.f32.f16.f16.f32 " \
    "{%0,%1,%2,%3}, {%4,%5,%6,%7}, {%8,%9}, {%0,%1,%2,%3};" \
    : "+f"((c)[0]), "+f"((c)[1]), "+f"((c)[2]), "+f"((c)[3]) \
    : "r"((a)[0]), "r"((a)[1]), "r"((a)[2]), "r"((a)[3]), \
      "r"((b)[0]), "r"((b)[1]))

// ---------------------------------------------------------------------------
// Prep: Wt[n][k] = W1[k][n] (n<128) | W1[128+k][n-128] (n>=128), as fp16.
// ---------------------------------------------------------------------------
__global__ void wt_kernel(const float* __restrict__ W1)
{
    int n = blockIdx.x;           // 0..255
    int k = threadIdx.x;          // 0..127
    float v = (n < HIDDEN) ? W1[k * HIDDEN + n]
                           : W1[(HIDDEN + k) * HIDDEN + (n - HIDDEN)];
    g_Wt[n * HIDDEN + k] = __float2half_rn(v);
}

// ---------------------------------------------------------------------------
// Phase 1: HMMA GEMM. Per CTA: D[128,256] = embtile[128,128] @ Wt^T.
// mma.sync.m16n8k16 fp16->fp32. 16 warps, warp tile 32x64.
// SMEM: A 128x(128 pad 136) fp16, B 256x(128 pad 136) fp16.
// ---------------------------------------------------------------------------
#define SMA_STRIDE 136
#define SA_OFF 0
#define SB_OFF (128 * SMA_STRIDE * 2)                  // 34816
#define SM_TOTAL (SB_OFF + 256 * SMA_STRIDE * 2)       // 104448

__global__ __launch_bounds__(512, 1)
void gemm_mma_kernel(const float* __restrict__ emb, const float* __restrict__ b1, int M)
{
    extern __shared__ char smem[];
    __half* SA = (__half*)(smem + SA_OFF);
    __half* SB = (__half*)(smem + SB_OFF);
    const int tid = threadIdx.x;
    const int lane = tid & 31;
    const int wid = tid >> 5;
    const int m0 = blockIdx.x * 128;

    // Load A tile: 128 rows x 128 k, fp32 -> fp16. 4096 float4, 8/thread.
#pragma unroll
    for (int i = 0; i < 8; i++) {
        int idx = tid + i * 512;          // 0..4095
        int row = idx >> 5;               // 0..127
        int k4  = (idx & 31) * 4;         // 0..124
        float4 v = make_float4(0.f, 0.f, 0.f, 0.f);
        if (m0 + row < M) v = *(const float4*)(emb + (size_t)(m0 + row) * HIDDEN + k4);
        __half2 h01 = __floats2half2_rn(v.x, v.y);
        __half2 h23 = __floats2half2_rn(v.z, v.w);
        uint2 pack = make_uint2(*(uint32_t*)&h01, *(uint32_t*)&h23);
        *(uint2*)(SA + row * SMA_STRIDE + k4) = pack;
    }
    // Load B tile: 256 n x 128 k fp16 from g_Wt. 8192 uint2, 16/thread.
#pragma unroll
    for (int i = 0; i < 16; i++) {
        int idx = tid + i * 512;          // 0..8191
        int n   = idx >> 5;               // 0..255
        int k4  = (idx & 31) * 4;
        uint2 v = *(const uint2*)(g_Wt + n * HIDDEN + k4);
        *(uint2*)(SB + n * SMA_STRIDE + k4) = v;
    }
    __syncthreads();

    // Warp tiling: 4 (M) x 4 (N) warps; warp tile 32 (M) x 64 (N).
    const int m_base = (wid >> 2) * 32;
    const int n_base = (wid & 3) * 64;
    const uint32_t sa = smem_u32(SA);
    const uint32_t sb = smem_u32(SB);

    float c[2][8][4];
#pragma unroll
    for (int mi = 0; mi < 2; mi++)
#pragma unroll
        for (int nj = 0; nj < 8; nj++)
#pragma unroll
            for (int q = 0; q < 4; q++) c[mi][nj][q] = 0.0f;

    // ldmatrix lane address components
    const int arow = (lane & 7) + ((lane >> 3) & 1) * 8;  // row within m16
    const int akh  = ((lane >> 4) & 1) * 8;               // k half
    const int brow = lane & 7;
    const int bsel = lane >> 3;                            // 0..3
    const int bnj  = (bsel >> 1) * 8;                      // n sub-block 0/8
    const int bkh  = (bsel & 1) * 8;                       // k half

#pragma unroll
    for (int ks = 0; ks < 8; ks++) {
        const int k0 = ks * 16;
        uint32_t a[2][4];
#pragma unroll
        for (int mi = 0; mi < 2; mi++) {
            uint32_t addr = sa + (uint32_t)(((m_base + mi * 16 + arow) * SMA_STRIDE
                                             + k0 + akh) * 2);
            LDSM_X4(a[mi][0], a[mi][1], a[mi][2], a[mi][3], addr);
        }
        uint32_t b[8][2];
#pragma unroll
        for (int p = 0; p < 4; p++) {   // each x4 covers 2 n-blocks
            uint32_t addr = sb + (uint32_t)(((n_base + p * 16 + bnj + brow) * SMA_STRIDE
                                             + k0 + bkh) * 2);
            uint32_t r0, r1, r2, r3;
            LDSM_X4(r0, r1, r2, r3, addr);
            b[p * 2][0] = r0; b[p * 2][1] = r1;
            b[p * 2 + 1][0] = r2; b[p * 2 + 1][1] = r3;
        }
#pragma unroll
        for (int mi = 0; mi < 2; mi++)
#pragma unroll
            for (int nj = 0; nj < 8; nj++)
                MMA16816(c[mi][nj], a[mi], b[nj]);
    }

    // Epilogue: accum frag (mi,nj): rows m_base+mi*16+(lane>>2){,+8},
    // cols n_base+nj*8+(lane&3)*2 (pair). Fold b1 for n<128; fp16 stores.
    const int ncol = (lane & 3) * 2;
    const int mrow = lane >> 2;
#pragma unroll
    for (int mi = 0; mi < 2; mi++) {
        const int r0 = m0 + m_base + mi * 16 + mrow;
        const int r1 = r0 + 8;
#pragma unroll
        for (int nj = 0; nj < 8; nj++) {
            int n = n_base + nj * 8 + ncol;
            float v0 = c[mi][nj][0], v1 = c[mi][nj][1];
            float v2 = c[mi][nj][2], v3 = c[mi][nj][3];
            if (n < HIDDEN) {
                float bb0 = __ldg(b1 + n), bb1 = __ldg(b1 + n + 1);
                v0 += bb0; v1 += bb1; v2 += bb0; v3 += bb1;
                __half2 h01 = __floats2half2_rn(v0, v1);
                __half2 h23 = __floats2half2_rn(v2, v3);
                if (r0 < M) *(__half2*)(g_A + (size_t)r0 * HIDDEN + n) = h01;
                if (r1 < M) *(__half2*)(g_A + (size_t)r1 * HIDDEN + n) = h23;
            } else {
                __half2 h01 = __floats2half2_rn(v0, v1);
                __half2 h23 = __floats2half2_rn(v2, v3);
                int nn = n - HIDDEN;
                if (r0 < M) *(__half2*)(g_B + (size_t)r0 * HIDDEN + nn) = h01;
                if (r1 < M) *(__half2*)(g_B + (size_t)r1 * HIDDEN + nn) = h23;
            }
        }
    }
}

// ---------------------------------------------------------------------------
// Phase 2: per-edge logit. One warp per edge: lane l handles features 4l..4l+3.
// ---------------------------------------------------------------------------
__global__ __launch_bounds__(256) void edge_kernel(
    const int* __restrict__ srcs, const int* __restrict__ dsts,
    const float* __restrict__ W2, const float* __restrict__ b2,
    int E, int M)
{
    const int lane = threadIdx.x & 31;
    const int warp = threadIdx.x >> 5;
    const int e = blockIdx.x * EDGES_PER_BLOCK + warp;

    float4 w2v = *(const float4*)(W2 + lane * 4);

    float logit = -CUDART_INF_F;
    if (e < E) {
        int s = srcs[e];
        int t = dsts[e];
        if ((unsigned)s >= (unsigned)M) s = 0;
        if ((unsigned)t >= (unsigned)M) t = 0;
        uint2 ar = *(const uint2*)(g_A + (size_t)s * HIDDEN + lane * 4);
        uint2 br = *(const uint2*)(g_B + (size_t)t * HIDDEN + lane * 4);
        float2 a01 = __half22float2(*(__half2*)&ar.x);
        float2 a23 = __half22float2(*(__half2*)&ar.y);
        float2 b01 = __half22float2(*(__half2*)&br.x);
        float2 b23 = __half22float2(*(__half2*)&br.y);
        float h0 = fmaxf(a01.x + b01.x, 0.0f);
        float h1 = fmaxf(a01.y + b01.y, 0.0f);
        float h2 = fmaxf(a23.x + b23.x, 0.0f);
        float h3 = fmaxf(a23.y + b23.y, 0.0f);
        float p = h0 * w2v.x + h1 * w2v.y + h2 * w2v.z + h3 * w2v.w;
#pragma unroll
        for (int o = 16; o > 0; o >>= 1)
            p += __shfl_down_sync(0xffffffffu, p, o);
        if (lane == 0) {
            logit = p + b2[0];
            g_logits[e] = logit;
        }
    }

    __shared__ float smax[EDGES_PER_BLOCK];
    if (lane == 0) smax[warp] = logit;
    __syncthreads();
    if (threadIdx.x == 0) {
        float m = smax[0];
#pragma unroll
        for (int i = 1; i < EDGES_PER_BLOCK; i++) m = fmaxf(m, smax[i]);
        g_pmax[blockIdx.x] = m;
    }
}

// ---------------------------------------------------------------------------
// Phase 3: softmax (deterministic two-level reductions)
// ---------------------------------------------------------------------------
__global__ __launch_bounds__(1024) void reduce_max_kernel(int n)
{
    __shared__ float s[1024];
    float m = -CUDART_INF_F;
    for (int i = threadIdx.x; i < n; i += 1024) m = fmaxf(m, g_pmax[i]);
    s[threadIdx.x] = m;
    __syncthreads();
#pragma unroll
    for (int o = 512; o > 0; o >>= 1) {
        if (threadIdx.x < o) s[threadIdx.x] = fmaxf(s[threadIdx.x], s[threadIdx.x + o]);
        __syncthreads();
    }
    if (threadIdx.x == 0) g_max = s[0];
}

__global__ __launch_bounds__(256) void exp_kernel(float* __restrict__ out, int E)
{
    const float m = g_max;
    float acc = 0.0f;
    for (int i = blockIdx.x * 256 + threadIdx.x; i < E; i += EXP_BLOCKS * 256) {
        float p = expf(g_logits[i] - m);
        out[i] = p;
        acc += p;
    }
    __shared__ float s[256];
    s[threadIdx.x] = acc;
    __syncthreads();
#pragma unroll
    for (int o = 128; o > 0; o >>= 1) {
        if (threadIdx.x < o) s[threadIdx.x] += s[threadIdx.x + o];
        __syncthreads();
    }
    if (threadIdx.x == 0) g_psum[blockIdx.x] = s[0];
}

__global__ __launch_bounds__(1024) void reduce_sum_kernel()
{
    __shared__ float s[1024];
    float a = 0.0f;
    for (int i = threadIdx.x; i < EXP_BLOCKS; i += 1024) a += g_psum[i];
    s[threadIdx.x] = a;
    __syncthreads();
#pragma unroll
    for (int o = 512; o > 0; o >>= 1) {
        if (threadIdx.x < o) s[threadIdx.x] += s[threadIdx.x + o];
        __syncthreads();
    }
    if (threadIdx.x == 0) g_inv = 1.0f / s[0];
}

__global__ __launch_bounds__(256) void scale_kernel(float* __restrict__ out, int E)
{
    const float v = g_inv;
    for (int i = blockIdx.x * 256 + threadIdx.x; i < E; i += EXP_BLOCKS * 256)
        out[i] *= v;
}

// ---------------------------------------------------------------------------
extern "C" void kernel_launch(void* const* d_in, const int* in_sizes, int n_in,
                              void* d_out, int out_size)
{
    const float* emb = (const float*)d_in[0];
    const int*   lm  = (const int*)d_in[1];   // int32 (JAX x64-disabled)
    const float* W1  = (const float*)d_in[2];
    const float* b1  = (const float*)d_in[3];
    const float* W2  = (const float*)d_in[4];
    const float* b2  = (const float*)d_in[5];
    float* out = (float*)d_out;

    const int M = in_sizes[0] / HIDDEN;       // number of nodes
    const int E = in_sizes[1] / 2;            // number of edges
    const int* srcs = lm;
    const int* dsts = lm + E;

    cudaFuncSetAttribute(gemm_mma_kernel,
                         cudaFuncAttributeMaxDynamicSharedMemorySize, SM_TOTAL);

    const int gemm_blocks = (M + 127) / 128;
    const int edge_blocks = (E + EDGES_PER_BLOCK - 1) / EDGES_PER_BLOCK;

    wt_kernel<<<256, 128>>>(W1);
    gemm_mma_kernel<<<gemm_blocks, 512, SM_TOTAL>>>(emb, b1, M);
    edge_kernel<<<edge_blocks, 256>>>(srcs, dsts, W2, b2, E, M);
    reduce_max_kernel<<<1, 1024>>>(edge_blocks);
    exp_kernel<<<EXP_BLOCKS, 256>>>(out, E);
    reduce_sum_kernel<<<1, 1024>>>();
    scale_kernel<<<EXP_BLOCKS, 256>>>(out, E);
}

// round 6
// speedup vs baseline: 1.7721x; 1.0595x over previous
#include <cuda_runtime.h>
#include <cuda_fp16.h>
#include <math_constants.h>
#include <cstdint>

// Problem constants (registry shapes)
#define MAX_NODES 100000
#define HIDDEN 128
#define MAX_EDGES 1000000

#define EDGES_PER_BLOCK 8
#define EXP_BLOCKS 2048

// Scratch (allocation-free rule: __device__ globals)
__device__ __half g_A[MAX_NODES * HIDDEN];      // emb @ W1[:128] + b1 (folded)
__device__ __half g_B[MAX_NODES * HIDDEN];      // emb @ W1[128:]
__device__ __half g_Wt[256 * 128];              // Wt[n][k] = Wcat[k][n], fp16
__device__ float g_logits[MAX_EDGES];
__device__ unsigned g_pmax2[256];               // bucketed max (orderable-uint keys)
__device__ float g_psum[EXP_BLOCKS];
__device__ float g_inv;

__device__ __forceinline__ uint32_t smem_u32(const void* p) {
    uint32_t a;
    asm("{ .reg .u64 t; cvta.to.shared.u64 t, %1; cvt.u32.u64 %0, t; }"
        : "=r"(a) : "l"(p));
    return a;
}

// float <-> monotone-orderable uint (max is order-independent => atomics OK)
__device__ __forceinline__ unsigned fenc(float f) {
    unsigned u = __float_as_uint(f);
    return (u & 0x80000000u) ? ~u : (u | 0x80000000u);
}
__device__ __forceinline__ float fdec(unsigned u) {
    unsigned b = (u & 0x80000000u) ? (u & 0x7FFFFFFFu) : ~u;
    return __uint_as_float(b);
}

#define LDSM_X4(r0, r1, r2, r3, addr) asm volatile( \
    "ldmatrix.sync.aligned.m8n8.x4.shared.b16 {%0,%1,%2,%3}, [%4];" \
    : "=r"(r0), "=r"(r1), "=r"(r2), "=r"(r3) : "r"(addr))

#define MMA16816(c, a, b) asm volatile( \
    "mma.sync.aligned.m16n8k16.row.col.f32.f16.f16.f32 " \
    "{%0,%1,%2,%3}, {%4,%5,%6,%7}, {%8,%9}, {%0,%1,%2,%3};" \
    : "+f"((c)[0]), "+f"((c)[1]), "+f"((c)[2]), "+f"((c)[3]) \
    : "r"((a)[0]), "r"((a)[1]), "r"((a)[2]), "r"((a)[3]), \
      "r"((b)[0]), "r"((b)[1]))

// ---------------------------------------------------------------------------
// Prep: Wt[n][k] = W1[k][n] (n<128) | W1[128+k][n-128] (n>=128), as fp16.
// Also initializes the 256 max buckets (blockIdx.x spans exactly 256).
// ---------------------------------------------------------------------------
__global__ void wt_kernel(const float* __restrict__ W1)
{
    int n = blockIdx.x;           // 0..255
    int k = threadIdx.x;          // 0..127
    if (k == 0) g_pmax2[n] = 0u;  // below fenc(-inf)=0x007FFFFF
    float v = (n < HIDDEN) ? W1[k * HIDDEN + n]
                           : W1[(HIDDEN + k) * HIDDEN + (n - HIDDEN)];
    g_Wt[n * HIDDEN + k] = __float2half_rn(v);
}

// ---------------------------------------------------------------------------
// Phase 1: HMMA GEMM, N-split for 2 CTAs/SM overlap.
// Per CTA: D[128,128] = embtile[128,128] @ Wt[nb*128 ..][128]^T.
// 256 threads (8 warps), warp tile 32x64 (4x2 warp grid).
// ---------------------------------------------------------------------------
#define SMA_STRIDE 136
#define SB_OFF (128 * SMA_STRIDE * 2)                  // 34816
#define SM_TOTAL (SB_OFF + 128 * SMA_STRIDE * 2)       // 69632

__global__ __launch_bounds__(256, 2)
void gemm_mma_kernel(const float* __restrict__ emb, const float* __restrict__ b1, int M)
{
    extern __shared__ char smem[];
    __half* SA = (__half*)smem;
    __half* SB = (__half*)(smem + SB_OFF);
    const int tid = threadIdx.x;
    const int lane = tid & 31;
    const int wid = tid >> 5;
    const int m0 = blockIdx.x * 128;
    const int nb = blockIdx.y;    // 0 -> g_A half, 1 -> g_B half

    // Load A tile: 128 rows x 128 k, fp32 -> fp16. 4096 float4, 16/thread.
#pragma unroll
    for (int i = 0; i < 16; i++) {
        int idx = tid + i * 256;          // 0..4095
        int row = idx >> 5;               // 0..127
        int k4  = (idx & 31) * 4;         // 0..124
        float4 v = make_float4(0.f, 0.f, 0.f, 0.f);
        if (m0 + row < M) v = *(const float4*)(emb + (size_t)(m0 + row) * HIDDEN + k4);
        __half2 h01 = __floats2half2_rn(v.x, v.y);
        __half2 h23 = __floats2half2_rn(v.z, v.w);
        uint2 pack = make_uint2(*(uint32_t*)&h01, *(uint32_t*)&h23);
        *(uint2*)(SA + row * SMA_STRIDE + k4) = pack;
    }
    // Load B half-tile: 128 n x 128 k fp16 from g_Wt. 4096 uint2, 16/thread.
    const __half* WtB = g_Wt + (size_t)nb * 128 * HIDDEN;
#pragma unroll
    for (int i = 0; i < 16; i++) {
        int idx = tid + i * 256;          // 0..4095
        int n   = idx >> 5;               // 0..127
        int k4  = (idx & 31) * 4;
        uint2 v = *(const uint2*)(WtB + n * HIDDEN + k4);
        *(uint2*)(SB + n * SMA_STRIDE + k4) = v;
    }
    __syncthreads();

    // Warp tiling: 4 (M) x 2 (N) warps; warp tile 32 (M) x 64 (N).
    const int m_base = (wid >> 1) * 32;
    const int n_base = (wid & 1) * 64;
    const uint32_t sa = smem_u32(SA);
    const uint32_t sb = smem_u32(SB);

    float c[2][8][4];
#pragma unroll
    for (int mi = 0; mi < 2; mi++)
#pragma unroll
        for (int nj = 0; nj < 8; nj++)
#pragma unroll
            for (int q = 0; q < 4; q++) c[mi][nj][q] = 0.0f;

    const int arow = (lane & 7) + ((lane >> 3) & 1) * 8;
    const int akh  = ((lane >> 4) & 1) * 8;
    const int brow = lane & 7;
    const int bsel = lane >> 3;
    const int bnj  = (bsel >> 1) * 8;
    const int bkh  = (bsel & 1) * 8;

#pragma unroll
    for (int ks = 0; ks < 8; ks++) {
        const int k0 = ks * 16;
        uint32_t a[2][4];
#pragma unroll
        for (int mi = 0; mi < 2; mi++) {
            uint32_t addr = sa + (uint32_t)(((m_base + mi * 16 + arow) * SMA_STRIDE
                                             + k0 + akh) * 2);
            LDSM_X4(a[mi][0], a[mi][1], a[mi][2], a[mi][3], addr);
        }
        uint32_t b[8][2];
#pragma unroll
        for (int p = 0; p < 4; p++) {
            uint32_t addr = sb + (uint32_t)(((n_base + p * 16 + bnj + brow) * SMA_STRIDE
                                             + k0 + bkh) * 2);
            uint32_t r0, r1, r2, r3;
            LDSM_X4(r0, r1, r2, r3, addr);
            b[p * 2][0] = r0; b[p * 2][1] = r1;
            b[p * 2 + 1][0] = r2; b[p * 2 + 1][1] = r3;
        }
#pragma unroll
        for (int mi = 0; mi < 2; mi++)
#pragma unroll
            for (int nj = 0; nj < 8; nj++)
                MMA16816(c[mi][nj], a[mi], b[nj]);
    }

    // Epilogue: local col n in [0,128). nb==0 -> g_A (+b1), nb==1 -> g_B.
    const int ncol = (lane & 3) * 2;
    const int mrow = lane >> 2;
    __half* dst_tbl = (nb == 0) ? g_A : g_B;
#pragma unroll
    for (int mi = 0; mi < 2; mi++) {
        const int r0 = m0 + m_base + mi * 16 + mrow;
        const int r1 = r0 + 8;
#pragma unroll
        for (int nj = 0; nj < 8; nj++) {
            int n = n_base + nj * 8 + ncol;
            float v0 = c[mi][nj][0], v1 = c[mi][nj][1];
            float v2 = c[mi][nj][2], v3 = c[mi][nj][3];
            if (nb == 0) {
                float bb0 = __ldg(b1 + n), bb1 = __ldg(b1 + n + 1);
                v0 += bb0; v1 += bb1; v2 += bb0; v3 += bb1;
            }
            __half2 h01 = __floats2half2_rn(v0, v1);
            __half2 h23 = __floats2half2_rn(v2, v3);
            if (r0 < M) *(__half2*)(dst_tbl + (size_t)r0 * HIDDEN + n) = h01;
            if (r1 < M) *(__half2*)(dst_tbl + (size_t)r1 * HIDDEN + n) = h23;
        }
    }
}

// ---------------------------------------------------------------------------
// Phase 2: per-edge logit. One warp per edge; block max -> bucketed atomicMax.
// ---------------------------------------------------------------------------
__global__ __launch_bounds__(256) void edge_kernel(
    const int* __restrict__ srcs, const int* __restrict__ dsts,
    const float* __restrict__ W2, const float* __restrict__ b2,
    int E, int M)
{
    const int lane = threadIdx.x & 31;
    const int warp = threadIdx.x >> 5;
    const int e = blockIdx.x * EDGES_PER_BLOCK + warp;

    float4 w2v = *(const float4*)(W2 + lane * 4);

    float logit = -CUDART_INF_F;
    if (e < E) {
        int s = srcs[e];
        int t = dsts[e];
        if ((unsigned)s >= (unsigned)M) s = 0;
        if ((unsigned)t >= (unsigned)M) t = 0;
        uint2 ar = *(const uint2*)(g_A + (size_t)s * HIDDEN + lane * 4);
        uint2 br = *(const uint2*)(g_B + (size_t)t * HIDDEN + lane * 4);
        float2 a01 = __half22float2(*(__half2*)&ar.x);
        float2 a23 = __half22float2(*(__half2*)&ar.y);
        float2 b01 = __half22float2(*(__half2*)&br.x);
        float2 b23 = __half22float2(*(__half2*)&br.y);
        float h0 = fmaxf(a01.x + b01.x, 0.0f);
        float h1 = fmaxf(a01.y + b01.y, 0.0f);
        float h2 = fmaxf(a23.x + b23.x, 0.0f);
        float h3 = fmaxf(a23.y + b23.y, 0.0f);
        float p = h0 * w2v.x + h1 * w2v.y + h2 * w2v.z + h3 * w2v.w;
#pragma unroll
        for (int o = 16; o > 0; o >>= 1)
            p += __shfl_down_sync(0xffffffffu, p, o);
        if (lane == 0) {
            logit = p + b2[0];
            g_logits[e] = logit;
        }
    }

    __shared__ float smax[EDGES_PER_BLOCK];
    if (lane == 0) smax[warp] = logit;
    __syncthreads();
    if (threadIdx.x == 0) {
        float m = smax[0];
#pragma unroll
        for (int i = 1; i < EDGES_PER_BLOCK; i++) m = fmaxf(m, smax[i]);
        atomicMax(&g_pmax2[blockIdx.x & 255], fenc(m));
    }
}

// ---------------------------------------------------------------------------
// Phase 3: softmax. exp_kernel folds the 256-bucket max into its preamble
// (exact & deterministic: max is order-independent).
// ---------------------------------------------------------------------------
__global__ __launch_bounds__(256) void exp_kernel(float* __restrict__ out, int E)
{
    __shared__ float s[256];
    s[threadIdx.x] = fdec(g_pmax2[threadIdx.x]);
    __syncthreads();
#pragma unroll
    for (int o = 128; o > 0; o >>= 1) {
        if (threadIdx.x < o) s[threadIdx.x] = fmaxf(s[threadIdx.x], s[threadIdx.x + o]);
        __syncthreads();
    }
    const float m = s[0];
    __syncthreads();

    float acc = 0.0f;
    for (int i = blockIdx.x * 256 + threadIdx.x; i < E; i += EXP_BLOCKS * 256) {
        float p = expf(g_logits[i] - m);
        out[i] = p;
        acc += p;
    }
    s[threadIdx.x] = acc;
    __syncthreads();
#pragma unroll
    for (int o = 128; o > 0; o >>= 1) {
        if (threadIdx.x < o) s[threadIdx.x] += s[threadIdx.x + o];
        __syncthreads();
    }
    if (threadIdx.x == 0) g_psum[blockIdx.x] = s[0];
}

__global__ __launch_bounds__(1024) void reduce_sum_kernel()
{
    __shared__ float s[1024];
    float a = 0.0f;
    for (int i = threadIdx.x; i < EXP_BLOCKS; i += 1024) a += g_psum[i];
    s[threadIdx.x] = a;
    __syncthreads();
#pragma unroll
    for (int o = 512; o > 0; o >>= 1) {
        if (threadIdx.x < o) s[threadIdx.x] += s[threadIdx.x + o];
        __syncthreads();
    }
    if (threadIdx.x == 0) g_inv = 1.0f / s[0];
}

__global__ __launch_bounds__(256) void scale_kernel(float* __restrict__ out, int E)
{
    const float v = g_inv;
    for (int i = blockIdx.x * 256 + threadIdx.x; i < E; i += EXP_BLOCKS * 256)
        out[i] *= v;
}

// ---------------------------------------------------------------------------
extern "C" void kernel_launch(void* const* d_in, const int* in_sizes, int n_in,
                              void* d_out, int out_size)
{
    const float* emb = (const float*)d_in[0];
    const int*   lm  = (const int*)d_in[1];   // int32 (JAX x64-disabled)
    const float* W1  = (const float*)d_in[2];
    const float* b1  = (const float*)d_in[3];
    const float* W2  = (const float*)d_in[4];
    const float* b2  = (const float*)d_in[5];
    float* out = (float*)d_out;

    const int M = in_sizes[0] / HIDDEN;       // number of nodes
    const int E = in_sizes[1] / 2;            // number of edges
    const int* srcs = lm;
    const int* dsts = lm + E;

    cudaFuncSetAttribute(gemm_mma_kernel,
                         cudaFuncAttributeMaxDynamicSharedMemorySize, SM_TOTAL);

    const int edge_blocks = (E + EDGES_PER_BLOCK - 1) / EDGES_PER_BLOCK;
    dim3 gemm_grid((M + 127) / 128, 2);

    wt_kernel<<<256, 128>>>(W1);
    gemm_mma_kernel<<<gemm_grid, 256, SM_TOTAL>>>(emb, b1, M);
    edge_kernel<<<edge_blocks, 256>>>(srcs, dsts, W2, b2, E, M);
    exp_kernel<<<EXP_BLOCKS, 256>>>(out, E);
    reduce_sum_kernel<<<1, 1024>>>();
    scale_kernel<<<EXP_BLOCKS, 256>>>(out, E);
}

// round 8
// speedup vs baseline: 2.5064x; 1.4144x over previous
#include <cuda_runtime.h>
#include <cuda_fp16.h>
#include <math_constants.h>
#include <cstdint>

// Problem constants (registry shapes)
#define MAX_NODES 100000
#define HIDDEN 128
#define MAX_EDGES 1000000

#define EXP_BLOCKS 1024

// Scratch (allocation-free rule: __device__ globals)
__device__ __half g_A[MAX_NODES * HIDDEN];      // emb @ W1[:128] + b1 (folded)
__device__ __half g_B[MAX_NODES * HIDDEN];      // emb @ W1[128:]
__device__ __half g_Wt[256 * 128];              // Wt[n][k] = Wcat[k][n], fp16
__device__ float g_logits[MAX_EDGES];
__device__ unsigned g_pmax2[256];               // bucketed max (orderable-uint keys)
__device__ float g_psum[EXP_BLOCKS];

__device__ __forceinline__ uint32_t smem_u32(const void* p) {
    uint32_t a;
    asm("{ .reg .u64 t; cvta.to.shared.u64 t, %1; cvt.u32.u64 %0, t; }"
        : "=r"(a) : "l"(p));
    return a;
}

// float <-> monotone-orderable uint (max is order-independent => atomics OK)
__device__ __forceinline__ unsigned fenc(float f) {
    unsigned u = __float_as_uint(f);
    return (u & 0x80000000u) ? ~u : (u | 0x80000000u);
}
__device__ __forceinline__ float fdec(unsigned u) {
    unsigned b = (u & 0x80000000u) ? (u & 0x7FFFFFFFu) : ~u;
    return __uint_as_float(b);
}

#define LDSM_X4(r0, r1, r2, r3, addr) asm volatile( \
    "ldmatrix.sync.aligned.m8n8.x4.shared.b16 {%0,%1,%2,%3}, [%4];" \
    : "=r"(r0), "=r"(r1), "=r"(r2), "=r"(r3) : "r"(addr))

#define MMA16816(c, a, b) asm volatile( \
    "mma.sync.aligned.m16n8k16.row.col.f32.f16.f16.f32 " \
    "{%0,%1,%2,%3}, {%4,%5,%6,%7}, {%8,%9}, {%0,%1,%2,%3};" \
    : "+f"((c)[0]), "+f"((c)[1]), "+f"((c)[2]), "+f"((c)[3]) \
    : "r"((a)[0]), "r"((a)[1]), "r"((a)[2]), "r"((a)[3]), \
      "r"((b)[0]), "r"((b)[1]))

// ---------------------------------------------------------------------------
// Prep: Wt[n][k] = W1[k][n] (n<128) | W1[128+k][n-128] (n>=128), as fp16.
// Also initializes the 256 max buckets (blockIdx.x spans exactly 256).
// ---------------------------------------------------------------------------
__global__ void wt_kernel(const float* __restrict__ W1)
{
    int n = blockIdx.x;           // 0..255
    int k = threadIdx.x;          // 0..127
    if (k == 0) g_pmax2[n] = 0u;
    float v = (n < HIDDEN) ? W1[k * HIDDEN + n]
                           : W1[(HIDDEN + k) * HIDDEN + (n - HIDDEN)];
    g_Wt[n * HIDDEN + k] = __float2half_rn(v);
}

// ---------------------------------------------------------------------------
// Phase 1: HMMA GEMM, N-split (grid.y: 0 -> g_A half +b1, 1 -> g_B half).
// Per CTA: D[128,128] = embtile[128,128] @ Wt-half^T. 256 threads, 8 warps,
// warp tile 32x64. Epilogue staged through SMEM for coalesced STG.128.
// ---------------------------------------------------------------------------
#define SMA_STRIDE 136
#define SB_OFF (128 * SMA_STRIDE * 2)                  // 34816
#define SM_TOTAL (SB_OFF + 128 * SMA_STRIDE * 2)       // 69632

__global__ __launch_bounds__(256, 2)
void gemm_mma_kernel(const float* __restrict__ emb, const float* __restrict__ b1, int M)
{
    extern __shared__ char smem[];
    __half* SA = (__half*)smem;
    __half* SB = (__half*)(smem + SB_OFF);
    const int tid = threadIdx.x;
    const int lane = tid & 31;
    const int wid = tid >> 5;
    const int m0 = blockIdx.x * 128;
    const int nb = blockIdx.y;

    // Load A tile: 128 rows x 128 k, fp32 -> fp16. 4096 float4, 16/thread.
#pragma unroll
    for (int i = 0; i < 16; i++) {
        int idx = tid + i * 256;
        int row = idx >> 5;
        int k4  = (idx & 31) * 4;
        float4 v = make_float4(0.f, 0.f, 0.f, 0.f);
        if (m0 + row < M) v = *(const float4*)(emb + (size_t)(m0 + row) * HIDDEN + k4);
        __half2 h01 = __floats2half2_rn(v.x, v.y);
        __half2 h23 = __floats2half2_rn(v.z, v.w);
        uint2 pack = make_uint2(*(uint32_t*)&h01, *(uint32_t*)&h23);
        *(uint2*)(SA + row * SMA_STRIDE + k4) = pack;
    }
    // Load B half-tile: 128 n x 128 k fp16 from g_Wt.
    const __half* WtB = g_Wt + (size_t)nb * 128 * HIDDEN;
#pragma unroll
    for (int i = 0; i < 16; i++) {
        int idx = tid + i * 256;
        int n   = idx >> 5;
        int k4  = (idx & 31) * 4;
        uint2 v = *(const uint2*)(WtB + n * HIDDEN + k4);
        *(uint2*)(SB + n * SMA_STRIDE + k4) = v;
    }
    __syncthreads();

    const int m_base = (wid >> 1) * 32;
    const int n_base = (wid & 1) * 64;
    const uint32_t sa = smem_u32(SA);
    const uint32_t sb = smem_u32(SB);

    float c[2][8][4];
#pragma unroll
    for (int mi = 0; mi < 2; mi++)
#pragma unroll
        for (int nj = 0; nj < 8; nj++)
#pragma unroll
            for (int q = 0; q < 4; q++) c[mi][nj][q] = 0.0f;

    const int arow = (lane & 7) + ((lane >> 3) & 1) * 8;
    const int akh  = ((lane >> 4) & 1) * 8;
    const int brow = lane & 7;
    const int bsel = lane >> 3;
    const int bnj  = (bsel >> 1) * 8;
    const int bkh  = (bsel & 1) * 8;

#pragma unroll
    for (int ks = 0; ks < 8; ks++) {
        const int k0 = ks * 16;
        uint32_t a[2][4];
#pragma unroll
        for (int mi = 0; mi < 2; mi++) {
            uint32_t addr = sa + (uint32_t)(((m_base + mi * 16 + arow) * SMA_STRIDE
                                             + k0 + akh) * 2);
            LDSM_X4(a[mi][0], a[mi][1], a[mi][2], a[mi][3], addr);
        }
        uint32_t b[8][2];
#pragma unroll
        for (int p = 0; p < 4; p++) {
            uint32_t addr = sb + (uint32_t)(((n_base + p * 16 + bnj + brow) * SMA_STRIDE
                                             + k0 + bkh) * 2);
            uint32_t r0, r1, r2, r3;
            LDSM_X4(r0, r1, r2, r3, addr);
            b[p * 2][0] = r0; b[p * 2][1] = r1;
            b[p * 2 + 1][0] = r2; b[p * 2 + 1][1] = r3;
        }
#pragma unroll
        for (int mi = 0; mi < 2; mi++)
#pragma unroll
            for (int nj = 0; nj < 8; nj++)
                MMA16816(c[mi][nj], a[mi], b[nj]);
    }

    // Epilogue stage 1: frags -> SA (stride 136 keeps STS conflict-free).
    __syncthreads();
    const int ncol = (lane & 3) * 2;
    const int mrow = lane >> 2;
#pragma unroll
    for (int mi = 0; mi < 2; mi++) {
        const int r0 = m_base + mi * 16 + mrow;
#pragma unroll
        for (int nj = 0; nj < 8; nj++) {
            int n = n_base + nj * 8 + ncol;
            float v0 = c[mi][nj][0], v1 = c[mi][nj][1];
            float v2 = c[mi][nj][2], v3 = c[mi][nj][3];
            if (nb == 0) {
                float bb0 = __ldg(b1 + n), bb1 = __ldg(b1 + n + 1);
                v0 += bb0; v1 += bb1; v2 += bb0; v3 += bb1;
            }
            *(__half2*)(SA + r0 * SMA_STRIDE + n)       = __floats2half2_rn(v0, v1);
            *(__half2*)(SA + (r0 + 8) * SMA_STRIDE + n) = __floats2half2_rn(v2, v3);
        }
    }
    __syncthreads();

    // Epilogue stage 2: coalesced STG.128. 2048 uint4, 8/thread.
    __half* dst_tbl = (nb == 0) ? g_A : g_B;
#pragma unroll
    for (int i = 0; i < 8; i++) {
        int idx = tid + i * 256;          // 0..2047
        int row = idx >> 4;               // 0..127
        int q   = (idx & 15) * 8;         // half offset within row
        if (m0 + row < M) {
            uint4 v = *(uint4*)(SA + row * SMA_STRIDE + q);
            *(uint4*)(dst_tbl + (size_t)(m0 + row) * HIDDEN + q) = v;
        }
    }
}

// ---------------------------------------------------------------------------
// Phase 2: per-edge logit. 8 lanes per edge, 4 edges per warp (MLP=8/warp).
// Lane handles features [sub*16, sub*16+16): a0/b0 = halves 0..7 of the
// slice (weights w[0..7]), a1/b1r = halves 8..15 (weights w[8..15]).
// ---------------------------------------------------------------------------
__global__ __launch_bounds__(256) void edge_kernel(
    const int* __restrict__ srcs, const int* __restrict__ dsts,
    const float* __restrict__ W2, const float* __restrict__ b2,
    int E, int M)
{
    const int lane = threadIdx.x & 31;
    const int warp = threadIdx.x >> 5;    // 0..7
    const int grp  = lane >> 3;           // 0..3 edge within warp
    const int sub  = lane & 7;            // 0..7 feature slice
    const int e = (blockIdx.x * 8 + warp) * 4 + grp;

    // 16 W2 coefficients for this lane's feature slice
    float w[16];
    {
        const float4* w2p = (const float4*)(W2 + sub * 16);
#pragma unroll
        for (int q = 0; q < 4; q++) {
            float4 v = w2p[q];
            w[q * 4 + 0] = v.x; w[q * 4 + 1] = v.y;
            w[q * 4 + 2] = v.z; w[q * 4 + 3] = v.w;
        }
    }
    const float b2v = __ldg(b2);

    const bool has = (e < E);
    float p = 0.0f;
    if (has) {
        int s = srcs[e];
        int t = dsts[e];
        if ((unsigned)s >= (unsigned)M) s = 0;
        if ((unsigned)t >= (unsigned)M) t = 0;
        const __half* Ar = g_A + (size_t)s * HIDDEN + sub * 16;
        const __half* Br = g_B + (size_t)t * HIDDEN + sub * 16;
        uint4 a0  = *(const uint4*)(Ar);
        uint4 a1  = *(const uint4*)(Ar + 8);
        uint4 b0  = *(const uint4*)(Br);
        uint4 b1r = *(const uint4*)(Br + 8);

        const uint32_t* au  = (const uint32_t*)&a0;   // 4 uint32 = halves 0..7
        const uint32_t* bu  = (const uint32_t*)&b0;
#pragma unroll
        for (int i = 0; i < 4; i++) {
            float2 af = __half22float2(*(__half2*)&au[i]);
            float2 bf = __half22float2(*(__half2*)&bu[i]);
            float h0 = fmaxf(af.x + bf.x, 0.0f);
            float h1 = fmaxf(af.y + bf.y, 0.0f);
            p = fmaf(h0, w[2 * i], p);
            p = fmaf(h1, w[2 * i + 1], p);
        }
        const uint32_t* au2 = (const uint32_t*)&a1;   // halves 8..15
        const uint32_t* bu2 = (const uint32_t*)&b1r;
#pragma unroll
        for (int i = 0; i < 4; i++) {
            float2 af = __half22float2(*(__half2*)&au2[i]);
            float2 bf = __half22float2(*(__half2*)&bu2[i]);
            float h0 = fmaxf(af.x + bf.x, 0.0f);
            float h1 = fmaxf(af.y + bf.y, 0.0f);
            p = fmaf(h0, w[8 + 2 * i], p);
            p = fmaf(h1, w[8 + 2 * i + 1], p);
        }
    }
    // reduce across the 8 lanes of the group
    p += __shfl_xor_sync(0xffffffffu, p, 4);
    p += __shfl_xor_sync(0xffffffffu, p, 2);
    p += __shfl_xor_sync(0xffffffffu, p, 1);
    const float logit = p + b2v;
    if (has && sub == 0) g_logits[e] = logit;

    // warp max over the 4 groups -> one bucketed atomic per warp
    float m = has ? logit : -CUDART_INF_F;
    m = fmaxf(m, __shfl_xor_sync(0xffffffffu, m, 8));
    m = fmaxf(m, __shfl_xor_sync(0xffffffffu, m, 16));
    if (lane == 0) atomicMax(&g_pmax2[blockIdx.x & 255], fenc(m));
}

// ---------------------------------------------------------------------------
// Phase 3: softmax. exp folds the 256-bucket max; scale folds the psum.
// ---------------------------------------------------------------------------
__global__ __launch_bounds__(256) void exp_kernel(float* __restrict__ out, int E)
{
    __shared__ float s[256];
    s[threadIdx.x] = fdec(g_pmax2[threadIdx.x]);
    __syncthreads();
#pragma unroll
    for (int o = 128; o > 0; o >>= 1) {
        if (threadIdx.x < o) s[threadIdx.x] = fmaxf(s[threadIdx.x], s[threadIdx.x + o]);
        __syncthreads();
    }
    const float m = s[0];
    __syncthreads();

    float acc = 0.0f;
    for (int i4 = (blockIdx.x * 256 + threadIdx.x) * 4; i4 < E; i4 += EXP_BLOCKS * 1024) {
        if (i4 + 3 < E) {
            float4 lg = *(const float4*)(g_logits + i4);
            float p0 = expf(lg.x - m), p1 = expf(lg.y - m);
            float p2 = expf(lg.z - m), p3 = expf(lg.w - m);
            *(float4*)(out + i4) = make_float4(p0, p1, p2, p3);
            acc += (p0 + p1) + (p2 + p3);
        } else {
            for (int i = i4; i < E; i++) {
                float p = expf(g_logits[i] - m);
                out[i] = p;
                acc += p;
            }
        }
    }
    s[threadIdx.x] = acc;
    __syncthreads();
#pragma unroll
    for (int o = 128; o > 0; o >>= 1) {
        if (threadIdx.x < o) s[threadIdx.x] += s[threadIdx.x + o];
        __syncthreads();
    }
    if (threadIdx.x == 0) g_psum[blockIdx.x] = s[0];
}

__global__ __launch_bounds__(256) void scale_kernel(float* __restrict__ out, int E)
{
    __shared__ float s[256];
    float a = 0.0f;
#pragma unroll
    for (int i = 0; i < EXP_BLOCKS / 256; i++)
        a += g_psum[threadIdx.x + i * 256];
    s[threadIdx.x] = a;
    __syncthreads();
#pragma unroll
    for (int o = 128; o > 0; o >>= 1) {
        if (threadIdx.x < o) s[threadIdx.x] += s[threadIdx.x + o];
        __syncthreads();
    }
    const float inv = 1.0f / s[0];

    for (int i4 = (blockIdx.x * 256 + threadIdx.x) * 4; i4 < E; i4 += 256 * 1024) {
        if (i4 + 3 < E) {
            float4 v = *(const float4*)(out + i4);
            v.x *= inv; v.y *= inv; v.z *= inv; v.w *= inv;
            *(float4*)(out + i4) = v;
        } else {
            for (int i = i4; i < E; i++) out[i] *= inv;
        }
    }
}

// ---------------------------------------------------------------------------
extern "C" void kernel_launch(void* const* d_in, const int* in_sizes, int n_in,
                              void* d_out, int out_size)
{
    const float* emb = (const float*)d_in[0];
    const int*   lm  = (const int*)d_in[1];   // int32 (JAX x64-disabled)
    const float* W1  = (const float*)d_in[2];
    const float* b1  = (const float*)d_in[3];
    const float* W2  = (const float*)d_in[4];
    const float* b2  = (const float*)d_in[5];
    float* out = (float*)d_out;

    const int M = in_sizes[0] / HIDDEN;       // number of nodes
    const int E = in_sizes[1] / 2;            // number of edges
    const int* srcs = lm;
    const int* dsts = lm + E;

    cudaFuncSetAttribute(gemm_mma_kernel,
                         cudaFuncAttributeMaxDynamicSharedMemorySize, SM_TOTAL);

    const int edge_blocks = (E + 31) / 32;    // 32 edges per block
    dim3 gemm_grid((M + 127) / 128, 2);

    wt_kernel<<<256, 128>>>(W1);
    gemm_mma_kernel<<<gemm_grid, 256, SM_TOTAL>>>(emb, b1, M);
    edge_kernel<<<edge_blocks, 256>>>(srcs, dsts, W2, b2, E, M);
    exp_kernel<<<EXP_BLOCKS, 256>>>(out, E);
    scale_kernel<<<256, 256>>>(out, E);
}